// round 6
// baseline (speedup 1.0000x reference)
#include <cuda_runtime.h>
#include <cuda_bf16.h>
#include <cstdint>
#include <math.h>

// Problem constants
#define NN   32768
#define KK   1024
#define QE   16777216

// Quantization scale: 127*(2^16+2^8+1); xs=+-1 -> digits (+-127,+-127,+-127) exact
#define QS   8355711.0f
#define C1   (256.0f / QS)
#define C0   (1.0f / QS)

// GEMM tiling: CTA = 128 rows x 128 codes, 256 thr = 8 warps (4M x 2N), warp 32x64
#define M_TILE 128
#define N_TILE 128
#define K_SLABS 16              // 512 ch / 32 per slab (32 B rows)
#define RS 48                   // smem row stride: 32 B data + 16 pad (3 mod 8 -> conflict-free)
#define PART_BYTES (128 * RS)   // 6144
#define STAGE_BYTES (4 * PART_BYTES)   // d2,d1,d0,B = 24576
#define GEMM_SMEM (2 * STAGE_BYTES)    // 49152
#define PREP_SMEM (3 * 32 * 516 + 2048)  // 51584

// Scratch. Digit planes slab-major: [slab 16][row NN][8 u32 (=32 s8)]
__device__ uint32_t g_d2[16 * NN * 8];
__device__ uint32_t g_d1[16 * NN * 8];
__device__ uint32_t g_d0[16 * NN * 8];
__device__ uint32_t g_cbs[16 * KK * 8];    // int8 codebook [slab][code][8 u32]
__device__ float g_x2[NN];
__device__ unsigned long long g_best[NN];
__device__ int g_cnt[KK];

__device__ __forceinline__ uint32_t smem_u32(const void* p) {
    return (uint32_t)__cvta_generic_to_shared(p);
}

#define LDSM4(r0, r1, r2, r3, addr)                                           \
    asm volatile("ldmatrix.sync.aligned.m8n8.x4.shared.b16 {%0,%1,%2,%3}, [%4];" \
                 : "=r"(r0), "=r"(r1), "=r"(r2), "=r"(r3) : "r"(addr))

#define IMMA16832(C, A, B0, B1)                                               \
    asm volatile("mma.sync.aligned.m16n8k32.row.col.s32.s8.s8.s32 "           \
                 "{%0,%1,%2,%3},{%4,%5,%6,%7},{%8,%9},{%0,%1,%2,%3};"         \
                 : "+r"((C)[0]), "+r"((C)[1]), "+r"((C)[2]), "+r"((C)[3])     \
                 : "r"((A)[0]), "r"((A)[1]), "r"((A)[2]), "r"((A)[3]),        \
                   "r"(B0), "r"(B1))

#define CP_ASYNC16(dst, src)                                                  \
    asm volatile("cp.async.cg.shared.global [%0], [%1], 16;" :: "r"(dst), "l"(src))
#define CP_COMMIT() asm volatile("cp.async.commit_group;")
#define CP_WAIT1()  asm volatile("cp.async.wait_group 1;")
#define CP_WAIT0()  asm volatile("cp.async.wait_group 0;")

// ---------------------------------------------------------------------------
__global__ void init_best_kernel() {
    int i = blockIdx.x * 256 + threadIdx.x;
    g_best[i] = 0xFFFFFFFFFFFFFFFFull;
}
__global__ void zero_counts_kernel() {
    int k = blockIdx.x * blockDim.x + threadIdx.x;
    if (k < KK) g_cnt[k] = 0;
}

// ---------------------------------------------------------------------------
// codebook fp32 (+-1) -> int8, slab-major packed
// ---------------------------------------------------------------------------
__global__ void cb_s8_kernel(const float* __restrict__ cb) {
    int i = blockIdx.x * 256 + threadIdx.x;    // 0..131071: code*128 + cw
    int code = i >> 7, cw = i & 127;
    float4 v = ((const float4*)cb)[i];
    uint32_t p = ((uint32_t)(uint8_t)(int8_t)(int)v.x)
               | ((uint32_t)(uint8_t)(int8_t)(int)v.y << 8)
               | ((uint32_t)(uint8_t)(int8_t)(int)v.z << 16)
               | ((uint32_t)(uint8_t)(int8_t)(int)v.w << 24);
    g_cbs[(((size_t)(cw >> 3)) * KK + code) * 8 + (cw & 7)] = p;
}

// ---------------------------------------------------------------------------
// prep: xs = tanh(50x) via FMA-only exp2 + Newton rcp; quantize to 3 balanced
// int8 digits of round(xs*QS); transpose to slab-major; ||xs||^2 + 512.
// ---------------------------------------------------------------------------
__global__ void __launch_bounds__(512, 2) prep_kernel(const float* __restrict__ x) {
    extern __shared__ char sm[];
    char* s_d[3] = { sm, sm + 32 * 516, sm + 2 * 32 * 516 };   // [32][516] each
    float* s_red = (float*)(sm + 3 * 32 * 516);                // [512]

    int tid = threadIdx.x;
    int b   = blockIdx.x >> 5;
    int p0  = (blockIdx.x & 31) * 32;
    int p   = tid & 31;
    int cg  = tid >> 5;         // 0..15

    float acc = 0.0f;
#pragma unroll 4
    for (int j = 0; j < 32; j++) {
        int c = j * 16 + cg;
        float v = x[(b * 512 + c) * 1024 + p0 + p];
        // m = exp(-100|v|) = 2^t
        float t = fmaxf(-144.26950408889634f * fabsf(v), -30.0f);
        float kf = t + 12582912.0f;
        int   ni = __float_as_int(kf) - 0x4B400000;
        float f  = t - (kf - 12582912.0f);
        float pe = 1.52527338e-5f;
        pe = fmaf(pe, f, 1.54035304e-4f);
        pe = fmaf(pe, f, 1.33335581e-3f);
        pe = fmaf(pe, f, 9.61812911e-3f);
        pe = fmaf(pe, f, 5.55041087e-2f);
        pe = fmaf(pe, f, 2.40226507e-1f);
        pe = fmaf(pe, f, 6.93147181e-1f);
        pe = fmaf(pe, f, 1.0f);
        float m = __int_as_float(__float_as_int(pe) + (ni << 23));
        // r = 1/(1+m), minimax seed on [1,2] + 3 Newton
        float den = 1.0f + m;
        float r = fmaf(-0.5f, den, 1.45710678f);
        r = r * fmaf(-den, r, 2.0f);
        r = r * fmaf(-den, r, 2.0f);
        r = r * fmaf(-den, r, 2.0f);
        float w = (1.0f - m) * r;
        float xs = copysignf(w, v);
        acc = fmaf(w, w, acc);
        // balanced base-256 digits of round(xs*QS)
        int q = __float2int_rn(xs * QS);
        int d0 = ((q + 128) & 255) - 128;  q = (q - d0) >> 8;
        int d1 = ((q + 128) & 255) - 128;  int d2 = (q - d1) >> 8;
        s_d[0][p * 516 + c] = (char)d2;
        s_d[1][p * 516 + c] = (char)d1;
        s_d[2][p * 516 + c] = (char)d0;
    }
    s_red[tid] = acc;
    __syncthreads();

    if (tid < 32) {
        float t = 0.0f;
#pragma unroll
        for (int g = 0; g < 16; g++) t += s_red[g * 32 + tid];
        g_x2[b * 1024 + p0 + tid] = t + 512.0f;
    }

    int nb = b * 1024 + p0;
    uint32_t* gp[3] = { g_d2, g_d1, g_d0 };
#pragma unroll
    for (int pl = 0; pl < 3; pl++) {
#pragma unroll
        for (int t = tid; t < 32 * 128; t += 512) {
            int r  = t >> 7;
            int cw = t & 127;
            uint32_t w = *(const uint32_t*)(s_d[pl] + r * 516 + cw * 4);
            gp[pl][(((size_t)(cw >> 3)) * NN + nb + r) * 8 + (cw & 7)] = w;
        }
    }
}

// ---------------------------------------------------------------------------
// int8 digit GEMM + fused argmin. grid = 256 M-tiles x 8 N-chunks (nc low bits).
// 256 threads = 8 warps (4M x 2N), warp tile 32x64, 3 persistent s32 acc sets.
// ---------------------------------------------------------------------------
__global__ void __launch_bounds__(256, 1) gemm_imma_kernel() {
    extern __shared__ char sm[];
    uint32_t smb = smem_u32(sm);

    int tid = threadIdx.x;
    int lane = tid & 31;
    int wid = tid >> 5;
    int wy = wid & 3;
    int wx = wid >> 2;          // 0..1
    int bid = blockIdx.x;
    int rowbase = (bid >> 3) * M_TILE;
    int colchunk = (bid & 7) * N_TILE;

    uint32_t tbaseA = (uint32_t)((wy * 32 + ((lane >> 3) & 1) * 8 + (lane & 7)) * RS
                                 + (lane >> 4) * 16);
    uint32_t tbaseB = (uint32_t)(((lane >> 4) * 8 + (lane & 7)) * RS
                                 + ((lane >> 3) & 1) * 16);

    const char* gA[3] = { (const char*)g_d2, (const char*)g_d1, (const char*)g_d0 };

    float x2v[4];
#pragma unroll
    for (int s = 0; s < 4; s++)
        x2v[s] = g_x2[rowbase + wy * 32 + (lane >> 2) + ((s & 1) ? 8 : 0) + (s >> 1) * 16];

    int acc[3][2][8][4];
#pragma unroll
    for (int pl = 0; pl < 3; pl++)
#pragma unroll
        for (int m = 0; m < 2; m++)
#pragma unroll
            for (int nf = 0; nf < 8; nf++)
#pragma unroll
                for (int j = 0; j < 4; j++) acc[pl][m][nf][j] = 0;

#define ISSUE_SLAB(slab, stage)                                               \
    {                                                                         \
        uint32_t dstbase = smb + (stage) * STAGE_BYTES;                       \
        int r = tid >> 1, half = tid & 1;                                     \
        _Pragma("unroll")                                                     \
        for (int part = 0; part < 3; part++) {                                \
            uint32_t dst = dstbase + part * PART_BYTES + r * RS + half * 16;  \
            const char* src = gA[part]                                        \
                + (((size_t)(slab) * NN + rowbase + r) << 5) + half * 16;     \
            CP_ASYNC16(dst, src);                                             \
        }                                                                     \
        {                                                                     \
            uint32_t dst = dstbase + 3 * PART_BYTES + r * RS + half * 16;     \
            const char* src = (const char*)g_cbs                              \
                + (((size_t)(slab) * KK + colchunk + r) << 5) + half * 16;    \
            CP_ASYNC16(dst, src);                                             \
        }                                                                     \
        CP_COMMIT();                                                          \
    }

    ISSUE_SLAB(0, 0);

    for (int s = 0; s < K_SLABS; s++) {
        if (s + 1 < K_SLABS) { ISSUE_SLAB(s + 1, (s + 1) & 1); CP_WAIT1(); }
        else                 { CP_WAIT0(); }
        __syncthreads();

        uint32_t sA = smb + (s & 1) * STAGE_BYTES;
        uint32_t sB = sA + 3 * PART_BYTES;

        uint32_t b[8][2];
#pragma unroll
        for (int q = 0; q < 4; q++) {
            uint32_t addr = sB + (uint32_t)((wx * 64 + q * 16) * RS) + tbaseB;
            LDSM4(b[2 * q][0], b[2 * q][1], b[2 * q + 1][0], b[2 * q + 1][1], addr);
        }
#pragma unroll
        for (int pl = 0; pl < 3; pl++) {
#pragma unroll
            for (int m = 0; m < 2; m++) {
                uint32_t a[4];
                LDSM4(a[0], a[1], a[2], a[3],
                      sA + pl * PART_BYTES + tbaseA + m * 16 * RS);
#pragma unroll
                for (int nf = 0; nf < 8; nf++)
                    IMMA16832(acc[pl][m][nf], a, b[nf][0], b[nf][1]);
            }
        }
        __syncthreads();
    }
#undef ISSUE_SLAB

    // epilogue: combine digit planes, distances, fused argmin (ascending idx)
    float bD[4] = {INFINITY, INFINITY, INFINITY, INFINITY};
    int   bI[4] = {0, 0, 0, 0};
    int colbase = colchunk + wx * 64 + (lane & 3) * 2;
#pragma unroll
    for (int nf = 0; nf < 8; nf++) {
        int cidx = colbase + nf * 8;
#pragma unroll
        for (int m = 0; m < 2; m++) {
#pragma unroll
            for (int j = 0; j < 4; j++) {
                int thi = acc[0][m][nf][j] * 256 + acc[1][m][nf][j];  // exact, < 2^24
                int tlo = acc[2][m][nf][j];
                float dot = fmaf((float)thi, C1, (float)tlo * C0);
                int sIdx = m * 2 + (j >> 1);
                float d = fmaf(-2.0f, dot, x2v[sIdx]);
                int ci = cidx + (j & 1);
                if (d < bD[sIdx]) { bD[sIdx] = d; bI[sIdx] = ci; }
            }
        }
    }

#pragma unroll
    for (int off = 1; off <= 2; off <<= 1) {
#pragma unroll
        for (int s = 0; s < 4; s++) {
            float od = __shfl_xor_sync(0xffffffffu, bD[s], off);
            int   oi = __shfl_xor_sync(0xffffffffu, bI[s], off);
            if (od < bD[s] || (od == bD[s] && oi < bI[s])) { bD[s] = od; bI[s] = oi; }
        }
    }

    if ((lane & 3) == 0) {
#pragma unroll
        for (int s = 0; s < 4; s++) {
            int row = rowbase + wy * 32 + (lane >> 2) + ((s & 1) ? 8 : 0) + (s >> 1) * 16;
            uint32_t u = __float_as_uint(bD[s]);
            u = (u & 0x80000000u) ? ~u : (u | 0x80000000u);
            unsigned long long key = ((unsigned long long)u << 32) | (unsigned)bI[s];
            atomicMin(&g_best[row], key);
        }
    }
}

// ---------------------------------------------------------------------------
__global__ void gather_kernel(const float* __restrict__ cb, float* __restrict__ out) {
    int t = blockIdx.x * blockDim.x + threadIdx.x;
    int n  = t & (NN - 1);
    int cg = t >> 15;
    int idx = (int)(unsigned)(g_best[n] & 0xffffffffu);
    float4 v = ((const float4*)cb)[idx * 128 + cg];
    int b = n >> 10, p = n & 1023;
    int c = cg << 2;
    float* o = out + (((size_t)(b * 512 + c)) << 10) + p;
    o[0]    = v.x;
    o[1024] = v.y;
    o[2048] = v.z;
    o[3072] = v.w;
}

__global__ void hist_kernel() {
    __shared__ int h[KK];
    int tid = threadIdx.x;
    for (int i = tid; i < KK; i += 256) h[i] = 0;
    __syncthreads();
    int base = blockIdx.x * 1024;
    for (int i = tid; i < 1024; i += 256)
        atomicAdd(&h[(int)(unsigned)(g_best[base + i] & 0xffffffffu)], 1);
    __syncthreads();
    for (int i = tid; i < KK; i += 256) if (h[i]) atomicAdd(&g_cnt[i], h[i]);
}

__global__ void entropy_kernel(float* __restrict__ out_scalars) {
    __shared__ float s[256];
    int tid = threadIdx.x;
    float acc = 0.0f;
    for (int k = tid; k < KK; k += 256) {
        int c = g_cnt[k];
        if (c > 0) {
            float p = (float)c / 32768.0f;
            acc += p * logf(p);
        }
    }
    s[tid] = acc;
    __syncthreads();
    for (int o = 128; o > 0; o >>= 1) {
        if (tid < o) s[tid] += s[tid + o];
        __syncthreads();
    }
    if (tid == 0) {
        float entropy = -s[0];
        float perp = expf(entropy);
        float pl = 1.0f / perp;
        out_scalars[0] = pl;
        out_scalars[1] = 0.25f * pl;
    }
}

// ---------------------------------------------------------------------------
extern "C" void kernel_launch(void* const* d_in, const int* in_sizes, int n_in,
                              void* d_out, int out_size) {
    const float* x  = (const float*)d_in[0];
    const float* cb = (const float*)d_in[1];
    float* out = (float*)d_out;

    cudaFuncSetAttribute(prep_kernel, cudaFuncAttributeMaxDynamicSharedMemorySize, PREP_SMEM);
    cudaFuncSetAttribute(gemm_imma_kernel, cudaFuncAttributeMaxDynamicSharedMemorySize, GEMM_SMEM);

    init_best_kernel<<<NN / 256, 256>>>();
    zero_counts_kernel<<<4, 256>>>();
    cb_s8_kernel<<<512, 256>>>(cb);
    prep_kernel<<<1024, 512, PREP_SMEM>>>(x);
    gemm_imma_kernel<<<(NN / M_TILE) * (KK / N_TILE), 256, GEMM_SMEM>>>();
    gather_kernel<<<(NN * 128) / 256, 256>>>(cb, out);
    hist_kernel<<<NN / 1024, 256>>>();
    if (out_size >= QE + 2) {
        entropy_kernel<<<1, 256>>>(out + QE);
    }
}

// round 7
// speedup vs baseline: 3.1065x; 3.1065x over previous
#include <cuda_runtime.h>
#include <cuda_fp16.h>
#include <cstdint>
#include <math.h>

// Problem constants
#define NN   32768
#define KK   1024
#define QE   16777216

// GEMM tiling: CTA = 128 rows x 256 codes, full K (512ch x 2 fp16 split planes)
#define M_TILE 128
#define N_TILE 256
#define K_SLABS 16             // 512 ch / 32 per slab
#define ROW_STRIDE 80          // 64B data + 16B pad (conflict-free ldsm)
#define A_PHASE_BYTES (128 * ROW_STRIDE)            // 10240
#define B_PHASE_BYTES (256 * ROW_STRIDE)            // 20480
#define STAGE_BYTES (2 * A_PHASE_BYTES + B_PHASE_BYTES)  // 40960
#define GEMM_SMEM (2 * STAGE_BYTES)                 // 81920
#define PREP_SMEM (65664 + 2048)

// Scratch (device globals; allocation-free). Slab-major:
// g_hi[slab 16][row 32768][16 u32] (16 u32 = 32 ch fp16 = 64B)
__device__ uint32_t g_hi[16 * NN * 16];
__device__ uint32_t g_mid[16 * NN * 16];
__device__ uint32_t g_cbh[16 * KK * 16];   // fp16 codebook [slab][code][16 u32]
__device__ float g_x2[NN];
__device__ unsigned long long g_best[NN];
__device__ int g_cnt[KK];

__device__ __forceinline__ uint32_t smem_u32(const void* p) {
    return (uint32_t)__cvta_generic_to_shared(p);
}

#define LDSM4(r0, r1, r2, r3, addr)                                           \
    asm volatile("ldmatrix.sync.aligned.m8n8.x4.shared.b16 {%0,%1,%2,%3}, [%4];" \
                 : "=r"(r0), "=r"(r1), "=r"(r2), "=r"(r3) : "r"(addr))

#define MMA16816(C, A, B0, B1)                                                \
    asm volatile("mma.sync.aligned.m16n8k16.row.col.f32.f16.f16.f32 "         \
                 "{%0,%1,%2,%3},{%4,%5,%6,%7},{%8,%9},{%0,%1,%2,%3};"         \
                 : "+f"((C)[0]), "+f"((C)[1]), "+f"((C)[2]), "+f"((C)[3])     \
                 : "r"((A)[0]), "r"((A)[1]), "r"((A)[2]), "r"((A)[3]),        \
                   "r"(B0), "r"(B1))

#define CP_ASYNC16(dst, src)                                                  \
    asm volatile("cp.async.cg.shared.global [%0], [%1], 16;" :: "r"(dst), "l"(src))
#define CP_COMMIT() asm volatile("cp.async.commit_group;")
#define CP_WAIT1()  asm volatile("cp.async.wait_group 1;")
#define CP_WAIT0()  asm volatile("cp.async.wait_group 0;")

// ---------------------------------------------------------------------------
__global__ void init_best_kernel() {
    int i = blockIdx.x * 256 + threadIdx.x;
    g_best[i] = 0xFFFFFFFFFFFFFFFFull;
}
__global__ void zero_counts_kernel() {
    int k = blockIdx.x * blockDim.x + threadIdx.x;
    if (k < KK) g_cnt[k] = 0;
}

// ---------------------------------------------------------------------------
// codebook fp32 (+-1) -> fp16 (exact), slab-major
// ---------------------------------------------------------------------------
__global__ void cb_f16_kernel(const float* __restrict__ cb) {
    int i = blockIdx.x * 256 + threadIdx.x;   // code*256 + cw
    int code = i >> 8, cw = i & 255;
    float2 v = ((const float2*)cb)[i];
    __half2 h2 = __floats2half2_rn(v.x, v.y);
    uint32_t u; memcpy(&u, &h2, 4);
    g_cbh[(((size_t)(cw >> 4)) * KK + code) * 16 + (cw & 15)] = u;
}

// ---------------------------------------------------------------------------
// prep: xs = tanh(50x) (== 2*sigmoid(100x)-1) via FMA-only exp2 + Newton rcp,
// 2-way fp16 split (hi+mid = xs to ~2^-24 abs), transpose slab-major,
// ||xs||^2 + 512.  512 threads: 32 p-values x 16 channel-groups.
// ---------------------------------------------------------------------------
__global__ void __launch_bounds__(512, 2) prep_kernel(const float* __restrict__ x) {
    extern __shared__ char sm[];
    uint32_t* s_hm = (uint32_t*)sm;             // [32][513]  (hi | mid<<16)
    float* s_red = (float*)(sm + 65664);        // [512]

    int tid = threadIdx.x;
    int b   = blockIdx.x >> 5;
    int p0  = (blockIdx.x & 31) * 32;
    int p   = tid & 31;
    int cg  = tid >> 5;         // 0..15

    float acc = 0.0f;
#pragma unroll 4
    for (int j = 0; j < 32; j++) {
        int c = j * 16 + cg;
        float v = x[(b * 512 + c) * 1024 + p0 + p];
        // m = exp(-100|v|) = 2^t, t = -144.2695*|v| (clamped at -30)
        float t = fmaxf(-144.26950408889634f * fabsf(v), -30.0f);
        float kf = t + 12582912.0f;
        int   ni = __float_as_int(kf) - 0x4B400000;
        float f  = t - (kf - 12582912.0f);
        float pe = 1.52527338e-5f;
        pe = fmaf(pe, f, 1.54035304e-4f);
        pe = fmaf(pe, f, 1.33335581e-3f);
        pe = fmaf(pe, f, 9.61812911e-3f);
        pe = fmaf(pe, f, 5.55041087e-2f);
        pe = fmaf(pe, f, 2.40226507e-1f);
        pe = fmaf(pe, f, 6.93147181e-1f);
        pe = fmaf(pe, f, 1.0f);
        float m = __int_as_float(__float_as_int(pe) + (ni << 23));
        // r = 1/(1+m), minimax linear seed on [1,2] + 3 Newton (~3e-9)
        float den = 1.0f + m;
        float r = fmaf(-0.5f, den, 1.45710678f);
        r = r * fmaf(-den, r, 2.0f);
        r = r * fmaf(-den, r, 2.0f);
        r = r * fmaf(-den, r, 2.0f);
        float w = (1.0f - m) * r;
        float xs = copysignf(w, v);
        acc = fmaf(w, w, acc);
        // 2-way fp16 split
        __half h = __float2half_rn(xs);
        float r1 = xs - __half2float(h);
        __half md = __float2half_rn(r1);
        s_hm[p * 513 + c] = (uint32_t)__half_as_ushort(h)
                          | ((uint32_t)__half_as_ushort(md) << 16);
    }
    s_red[tid] = acc;
    __syncthreads();

    if (tid < 32) {
        float t = 0.0f;
#pragma unroll
        for (int g = 0; g < 16; g++) t += s_red[g * 32 + tid];
        g_x2[b * 1024 + p0 + tid] = t + 512.0f;
    }

    int nb = b * 1024 + p0;
#pragma unroll 4
    for (int t = tid; t < 32 * 256; t += 512) {
        int r  = t >> 8;
        int cw = t & 255;
        uint32_t hm0 = s_hm[r * 513 + 2 * cw];
        uint32_t hm1 = s_hm[r * 513 + 2 * cw + 1];
        uint32_t hi_pair  = (hm0 & 0xffffu) | (hm1 << 16);
        uint32_t mid_pair = (hm0 >> 16) | (hm1 & 0xffff0000u);
        size_t gi = (((size_t)(cw >> 4)) * NN + nb + r) * 16 + (cw & 15);
        g_hi[gi]  = hi_pair;
        g_mid[gi] = mid_pair;
    }
}

// ---------------------------------------------------------------------------
// GEMM + fused argmin. grid = 256 M-tiles x 4 N-chunks (nc in low bits).
// 512 threads = 16 warps (4M x 4N), warp tile 32x64, 2 fp16 split planes.
// ---------------------------------------------------------------------------
__global__ void __launch_bounds__(512, 1) gemm_hmma_kernel() {
    extern __shared__ char sm[];
    uint32_t smb = smem_u32(sm);

    int tid = threadIdx.x;
    int lane = tid & 31;
    int wid = tid >> 5;
    int wy = wid & 3;
    int wx = wid >> 2;          // 0..3
    int bid = blockIdx.x;
    int mt = bid >> 2;
    int nc = bid & 3;
    int rowbase = mt * M_TILE;
    int colchunk = nc * N_TILE;

    uint32_t tbaseA = (uint32_t)((wy * 32 + ((lane >> 3) & 1) * 8 + (lane & 7)) * ROW_STRIDE
                                 + (lane >> 4) * 16);
    uint32_t tbaseB = (uint32_t)(((lane >> 4) * 8 + (lane & 7)) * ROW_STRIDE
                                 + ((lane >> 3) & 1) * 16);

    const char* gA[2] = { (const char*)g_hi, (const char*)g_mid };

    float x2v[4];
#pragma unroll
    for (int s = 0; s < 4; s++)
        x2v[s] = g_x2[rowbase + wy * 32 + (lane >> 2) + ((s & 1) ? 8 : 0) + (s >> 1) * 16];

    float bD[4] = {INFINITY, INFINITY, INFINITY, INFINITY};
    int   bI[4] = {0, 0, 0, 0};

    float acc[2][8][4];
#pragma unroll
    for (int m = 0; m < 2; m++)
#pragma unroll
        for (int nf = 0; nf < 8; nf++)
#pragma unroll
            for (int j = 0; j < 4; j++) acc[m][nf][j] = 0.0f;

#define ISSUE_SLAB(slab, stage)                                               \
    {                                                                         \
        uint32_t dstbase = smb + (stage) * STAGE_BYTES;                       \
        _Pragma("unroll")                                                     \
        for (int i = 0; i < 4; i++) {                                         \
            int id = tid + i * 512;                                           \
            if (id < 1024) {                                                  \
                int part = id >> 9;                                           \
                int r = (id >> 2) & 127;                                      \
                int c = id & 3;                                               \
                uint32_t dst = dstbase + part * A_PHASE_BYTES                 \
                             + r * ROW_STRIDE + c * 16;                       \
                const char* src = gA[part]                                    \
                    + ((size_t)(slab) * NN + rowbase + r) * 64 + c * 16;      \
                CP_ASYNC16(dst, src);                                         \
            } else {                                                          \
                int id2 = id - 1024;                                          \
                int r = id2 >> 2;                                             \
                int c = id2 & 3;                                              \
                uint32_t dst = dstbase + 2 * A_PHASE_BYTES                    \
                             + r * ROW_STRIDE + c * 16;                       \
                const char* src = (const char*)g_cbh                          \
                    + ((size_t)(slab) * KK + colchunk + r) * 64 + c * 16;     \
                CP_ASYNC16(dst, src);                                         \
            }                                                                 \
        }                                                                     \
        CP_COMMIT();                                                          \
    }

    ISSUE_SLAB(0, 0);

    for (int s = 0; s < K_SLABS; s++) {
        if (s + 1 < K_SLABS) { ISSUE_SLAB(s + 1, (s + 1) & 1); CP_WAIT1(); }
        else                 { CP_WAIT0(); }
        __syncthreads();

        uint32_t sA = smb + (s & 1) * STAGE_BYTES;
        uint32_t sB = sA + 2 * A_PHASE_BYTES;
#pragma unroll
        for (int kk = 0; kk < 2; kk++) {
            uint32_t b[8][2];
#pragma unroll
            for (int q = 0; q < 4; q++) {
                uint32_t addr = sB + (uint32_t)((wx * 64 + q * 16) * ROW_STRIDE)
                              + tbaseB + kk * 32;
                LDSM4(b[2 * q][0], b[2 * q][1], b[2 * q + 1][0], b[2 * q + 1][1], addr);
            }
#pragma unroll
            for (int p = 0; p < 2; p++) {
                uint32_t a0[4], a1[4];
                uint32_t aaddr = sA + p * A_PHASE_BYTES + tbaseA + kk * 32;
                LDSM4(a0[0], a0[1], a0[2], a0[3], aaddr);
                LDSM4(a1[0], a1[1], a1[2], a1[3], aaddr + 16 * ROW_STRIDE);
#pragma unroll
                for (int nf = 0; nf < 8; nf++) {
                    MMA16816(acc[0][nf], a0, b[nf][0], b[nf][1]);
                    MMA16816(acc[1][nf], a1, b[nf][0], b[nf][1]);
                }
            }
        }
        __syncthreads();
    }
#undef ISSUE_SLAB

    // fused argmin over this chunk's 256 columns (ascending index)
    int colbase = colchunk + wx * 64 + (lane & 3) * 2;
#pragma unroll
    for (int nf = 0; nf < 8; nf++) {
        int cidx = colbase + nf * 8;
#pragma unroll
        for (int m = 0; m < 2; m++) {
            float d0 = fmaf(-2.0f, acc[m][nf][0], x2v[m * 2]);
            float d1 = fmaf(-2.0f, acc[m][nf][1], x2v[m * 2]);
            float d2 = fmaf(-2.0f, acc[m][nf][2], x2v[m * 2 + 1]);
            float d3 = fmaf(-2.0f, acc[m][nf][3], x2v[m * 2 + 1]);
            if (d0 < bD[m * 2])     { bD[m * 2] = d0;     bI[m * 2] = cidx; }
            if (d1 < bD[m * 2])     { bD[m * 2] = d1;     bI[m * 2] = cidx + 1; }
            if (d2 < bD[m * 2 + 1]) { bD[m * 2 + 1] = d2; bI[m * 2 + 1] = cidx; }
            if (d3 < bD[m * 2 + 1]) { bD[m * 2 + 1] = d3; bI[m * 2 + 1] = cidx + 1; }
        }
    }

#pragma unroll
    for (int off = 1; off <= 2; off <<= 1) {
#pragma unroll
        for (int s = 0; s < 4; s++) {
            float od = __shfl_xor_sync(0xffffffffu, bD[s], off);
            int   oi = __shfl_xor_sync(0xffffffffu, bI[s], off);
            if (od < bD[s] || (od == bD[s] && oi < bI[s])) { bD[s] = od; bI[s] = oi; }
        }
    }

    if ((lane & 3) == 0) {
#pragma unroll
        for (int s = 0; s < 4; s++) {
            int row = rowbase + wy * 32 + (lane >> 2) + ((s & 1) ? 8 : 0) + (s >> 1) * 16;
            uint32_t u = __float_as_uint(bD[s]);
            u = (u & 0x80000000u) ? ~u : (u | 0x80000000u);
            unsigned long long key = ((unsigned long long)u << 32) | (unsigned)bI[s];
            atomicMin(&g_best[row], key);
        }
    }
}

// ---------------------------------------------------------------------------
__global__ void gather_kernel(const float* __restrict__ cb, float* __restrict__ out) {
    int t = blockIdx.x * blockDim.x + threadIdx.x;
    int n  = t & (NN - 1);
    int cg = t >> 15;
    int idx = (int)(unsigned)(g_best[n] & 0xffffffffu);
    float4 v = ((const float4*)cb)[idx * 128 + cg];
    int b = n >> 10, p = n & 1023;
    int c = cg << 2;
    float* o = out + (((size_t)(b * 512 + c)) << 10) + p;
    o[0]    = v.x;
    o[1024] = v.y;
    o[2048] = v.z;
    o[3072] = v.w;
}

__global__ void hist_kernel() {
    __shared__ int h[KK];
    int tid = threadIdx.x;
    for (int i = tid; i < KK; i += 256) h[i] = 0;
    __syncthreads();
    int base = blockIdx.x * 1024;
    for (int i = tid; i < 1024; i += 256)
        atomicAdd(&h[(int)(unsigned)(g_best[base + i] & 0xffffffffu)], 1);
    __syncthreads();
    for (int i = tid; i < KK; i += 256) if (h[i]) atomicAdd(&g_cnt[i], h[i]);
}

__global__ void entropy_kernel(float* __restrict__ out_scalars) {
    __shared__ float s[256];
    int tid = threadIdx.x;
    float acc = 0.0f;
    for (int k = tid; k < KK; k += 256) {
        int c = g_cnt[k];
        if (c > 0) {
            float p = (float)c / 32768.0f;
            acc += p * logf(p);
        }
    }
    s[tid] = acc;
    __syncthreads();
    for (int o = 128; o > 0; o >>= 1) {
        if (tid < o) s[tid] += s[tid + o];
        __syncthreads();
    }
    if (tid == 0) {
        float entropy = -s[0];
        float perp = expf(entropy);
        float pl = 1.0f / perp;
        out_scalars[0] = pl;
        out_scalars[1] = 0.25f * pl;
    }
}

// ---------------------------------------------------------------------------
extern "C" void kernel_launch(void* const* d_in, const int* in_sizes, int n_in,
                              void* d_out, int out_size) {
    const float* x  = (const float*)d_in[0];
    const float* cb = (const float*)d_in[1];
    float* out = (float*)d_out;

    cudaFuncSetAttribute(prep_kernel, cudaFuncAttributeMaxDynamicSharedMemorySize, PREP_SMEM);
    cudaFuncSetAttribute(gemm_hmma_kernel, cudaFuncAttributeMaxDynamicSharedMemorySize, GEMM_SMEM);

    init_best_kernel<<<NN / 256, 256>>>();
    zero_counts_kernel<<<4, 256>>>();
    cb_f16_kernel<<<1024, 256>>>(cb);
    prep_kernel<<<1024, 512, PREP_SMEM>>>(x);
    gemm_hmma_kernel<<<(NN / M_TILE) * (KK / N_TILE), 512, GEMM_SMEM>>>();
    gather_kernel<<<(NN * 128) / 256, 256>>>(cb, out);
    hist_kernel<<<NN / 1024, 256>>>();
    if (out_size >= QE + 2) {
        entropy_kernel<<<1, 256>>>(out + QE);
    }
}

// round 8
// speedup vs baseline: 3.2130x; 1.0343x over previous
#include <cuda_runtime.h>
#include <cuda_fp16.h>
#include <cstdint>
#include <math.h>

// Problem constants
#define NN   32768
#define KK   1024
#define QE   16777216

// GEMM tiling: CTA = 128 rows x 256 codes, full K (512ch x 2 fp16 split planes)
#define M_TILE 128
#define N_TILE 256
#define K_SLABS 16             // 512 ch / 32 per slab
#define ROW_STRIDE 80          // 64B data + 16B pad (conflict-free ldsm)
#define A_PHASE_BYTES (128 * ROW_STRIDE)            // 10240
#define B_PHASE_BYTES (256 * ROW_STRIDE)            // 20480
#define STAGE_BYTES (2 * A_PHASE_BYTES + B_PHASE_BYTES)  // 40960
#define N_STAGES 3
#define GEMM_SMEM (N_STAGES * STAGE_BYTES)          // 122880
#define PREP_SMEM (65664 + 2048)

// Scratch (device globals; allocation-free). Slab-major:
// g_hi[slab 16][row 32768][16 u32] (16 u32 = 32 ch fp16 = 64B)
__device__ uint32_t g_hi[16 * NN * 16];
__device__ uint32_t g_mid[16 * NN * 16];
__device__ uint32_t g_cbh[16 * KK * 16];   // fp16 codebook [slab][code][16 u32]
__device__ float g_x2[NN];
__device__ unsigned long long g_best[NN];
__device__ int g_cnt[KK];

__device__ __forceinline__ uint32_t smem_u32(const void* p) {
    return (uint32_t)__cvta_generic_to_shared(p);
}

#define LDSM4(r0, r1, r2, r3, addr)                                           \
    asm volatile("ldmatrix.sync.aligned.m8n8.x4.shared.b16 {%0,%1,%2,%3}, [%4];" \
                 : "=r"(r0), "=r"(r1), "=r"(r2), "=r"(r3) : "r"(addr))

#define MMA16816(C, A, B0, B1)                                                \
    asm volatile("mma.sync.aligned.m16n8k16.row.col.f32.f16.f16.f32 "         \
                 "{%0,%1,%2,%3},{%4,%5,%6,%7},{%8,%9},{%0,%1,%2,%3};"         \
                 : "+f"((C)[0]), "+f"((C)[1]), "+f"((C)[2]), "+f"((C)[3])     \
                 : "r"((A)[0]), "r"((A)[1]), "r"((A)[2]), "r"((A)[3]),        \
                   "r"(B0), "r"(B1))

#define CP_ASYNC16(dst, src)                                                  \
    asm volatile("cp.async.cg.shared.global [%0], [%1], 16;" :: "r"(dst), "l"(src))
#define CP_COMMIT() asm volatile("cp.async.commit_group;")
#define CP_WAIT1()  asm volatile("cp.async.wait_group 1;")
#define CP_WAIT0()  asm volatile("cp.async.wait_group 0;")

// ---------------------------------------------------------------------------
// init: g_best = +inf keys, g_cnt = 0 (one kernel)
// ---------------------------------------------------------------------------
__global__ void init_kernel() {
    int i = blockIdx.x * 256 + threadIdx.x;
    g_best[i] = 0xFFFFFFFFFFFFFFFFull;
    if (i < KK) g_cnt[i] = 0;
}

// ---------------------------------------------------------------------------
// codebook fp32 (+-1) -> fp16 (exact), slab-major
// ---------------------------------------------------------------------------
__global__ void cb_f16_kernel(const float* __restrict__ cb) {
    int i = blockIdx.x * 256 + threadIdx.x;   // code*256 + cw
    int code = i >> 8, cw = i & 255;
    float2 v = ((const float2*)cb)[i];
    __half2 h2 = __floats2half2_rn(v.x, v.y);
    uint32_t u; memcpy(&u, &h2, 4);
    g_cbh[(((size_t)(cw >> 4)) * KK + code) * 16 + (cw & 15)] = u;
}

// ---------------------------------------------------------------------------
// prep: xs = tanh(50x) via FMA-only exp2 + Newton rcp, 2-way fp16 split,
// transpose slab-major, ||xs||^2 + 512.
// ---------------------------------------------------------------------------
__global__ void __launch_bounds__(512, 2) prep_kernel(const float* __restrict__ x) {
    extern __shared__ char sm[];
    uint32_t* s_hm = (uint32_t*)sm;             // [32][513]  (hi | mid<<16)
    float* s_red = (float*)(sm + 65664);        // [512]

    int tid = threadIdx.x;
    int b   = blockIdx.x >> 5;
    int p0  = (blockIdx.x & 31) * 32;
    int p   = tid & 31;
    int cg  = tid >> 5;         // 0..15

    float acc = 0.0f;
#pragma unroll 4
    for (int j = 0; j < 32; j++) {
        int c = j * 16 + cg;
        float v = x[(b * 512 + c) * 1024 + p0 + p];
        float t = fmaxf(-144.26950408889634f * fabsf(v), -30.0f);
        float kf = t + 12582912.0f;
        int   ni = __float_as_int(kf) - 0x4B400000;
        float f  = t - (kf - 12582912.0f);
        float pe = 1.52527338e-5f;
        pe = fmaf(pe, f, 1.54035304e-4f);
        pe = fmaf(pe, f, 1.33335581e-3f);
        pe = fmaf(pe, f, 9.61812911e-3f);
        pe = fmaf(pe, f, 5.55041087e-2f);
        pe = fmaf(pe, f, 2.40226507e-1f);
        pe = fmaf(pe, f, 6.93147181e-1f);
        pe = fmaf(pe, f, 1.0f);
        float m = __int_as_float(__float_as_int(pe) + (ni << 23));
        float den = 1.0f + m;
        float r = fmaf(-0.5f, den, 1.45710678f);
        r = r * fmaf(-den, r, 2.0f);
        r = r * fmaf(-den, r, 2.0f);
        r = r * fmaf(-den, r, 2.0f);
        float w = (1.0f - m) * r;
        float xs = copysignf(w, v);
        acc = fmaf(w, w, acc);
        __half h = __float2half_rn(xs);
        float r1 = xs - __half2float(h);
        __half md = __float2half_rn(r1);
        s_hm[p * 513 + c] = (uint32_t)__half_as_ushort(h)
                          | ((uint32_t)__half_as_ushort(md) << 16);
    }
    s_red[tid] = acc;
    __syncthreads();

    if (tid < 32) {
        float t = 0.0f;
#pragma unroll
        for (int g = 0; g < 16; g++) t += s_red[g * 32 + tid];
        g_x2[b * 1024 + p0 + tid] = t + 512.0f;
    }

    int nb = b * 1024 + p0;
#pragma unroll 4
    for (int t = tid; t < 32 * 256; t += 512) {
        int r  = t >> 8;
        int cw = t & 255;
        uint32_t hm0 = s_hm[r * 513 + 2 * cw];
        uint32_t hm1 = s_hm[r * 513 + 2 * cw + 1];
        uint32_t hi_pair  = (hm0 & 0xffffu) | (hm1 << 16);
        uint32_t mid_pair = (hm0 >> 16) | (hm1 & 0xffff0000u);
        size_t gi = (((size_t)(cw >> 4)) * NN + nb + r) * 16 + (cw & 15);
        g_hi[gi]  = hi_pair;
        g_mid[gi] = mid_pair;
    }
}

// ---------------------------------------------------------------------------
// GEMM + fused argmin. grid = 256 M-tiles x 4 N-chunks (nc in low bits).
// 512 threads = 16 warps (4M x 4N), warp tile 32x64, 2 fp16 split planes.
// 3-stage cp.async pipeline, one __syncthreads per slab.
// ---------------------------------------------------------------------------
__global__ void __launch_bounds__(512, 1) gemm_hmma_kernel() {
    extern __shared__ char sm[];
    uint32_t smb = smem_u32(sm);

    int tid = threadIdx.x;
    int lane = tid & 31;
    int wid = tid >> 5;
    int wy = wid & 3;
    int wx = wid >> 2;          // 0..3
    int bid = blockIdx.x;
    int mt = bid >> 2;
    int nc = bid & 3;
    int rowbase = mt * M_TILE;
    int colchunk = nc * N_TILE;

    uint32_t tbaseA = (uint32_t)((wy * 32 + ((lane >> 3) & 1) * 8 + (lane & 7)) * ROW_STRIDE
                                 + (lane >> 4) * 16);
    uint32_t tbaseB = (uint32_t)(((lane >> 4) * 8 + (lane & 7)) * ROW_STRIDE
                                 + ((lane >> 3) & 1) * 16);

    const char* gA[2] = { (const char*)g_hi, (const char*)g_mid };

    float x2v[4];
#pragma unroll
    for (int s = 0; s < 4; s++)
        x2v[s] = g_x2[rowbase + wy * 32 + (lane >> 2) + ((s & 1) ? 8 : 0) + (s >> 1) * 16];

    float bD[4] = {INFINITY, INFINITY, INFINITY, INFINITY};
    int   bI[4] = {0, 0, 0, 0};

    float acc[2][8][4];
#pragma unroll
    for (int m = 0; m < 2; m++)
#pragma unroll
        for (int nf = 0; nf < 8; nf++)
#pragma unroll
            for (int j = 0; j < 4; j++) acc[m][nf][j] = 0.0f;

#define ISSUE_SLAB(slab, stage)                                               \
    {                                                                         \
        uint32_t dstbase = smb + (stage) * STAGE_BYTES;                       \
        _Pragma("unroll")                                                     \
        for (int i = 0; i < 4; i++) {                                         \
            int id = tid + i * 512;                                           \
            if (id < 1024) {                                                  \
                int part = id >> 9;                                           \
                int r = (id >> 2) & 127;                                      \
                int c = id & 3;                                               \
                uint32_t dst = dstbase + part * A_PHASE_BYTES                 \
                             + r * ROW_STRIDE + c * 16;                       \
                const char* src = gA[part]                                    \
                    + ((size_t)(slab) * NN + rowbase + r) * 64 + c * 16;      \
                CP_ASYNC16(dst, src);                                         \
            } else {                                                          \
                int id2 = id - 1024;                                          \
                int r = id2 >> 2;                                             \
                int c = id2 & 3;                                              \
                uint32_t dst = dstbase + 2 * A_PHASE_BYTES                    \
                             + r * ROW_STRIDE + c * 16;                       \
                const char* src = (const char*)g_cbh                          \
                    + ((size_t)(slab) * KK + colchunk + r) * 64 + c * 16;     \
                CP_ASYNC16(dst, src);                                         \
            }                                                                 \
        }                                                                     \
        CP_COMMIT();                                                          \
    }

    // prologue: two slabs in flight
    ISSUE_SLAB(0, 0);
    ISSUE_SLAB(1, 1);

    int st0 = 0;                // stage of slab s
    for (int s = 0; s < K_SLABS; s++) {
        if (s + 1 < K_SLABS) { CP_WAIT1(); } else { CP_WAIT0(); }
        __syncthreads();

        // issue s+2 into the stage freed by slab s-1 (readers done at the sync)
        if (s + 2 < K_SLABS) {
            int st2 = st0 + 2; if (st2 >= N_STAGES) st2 -= N_STAGES;
            ISSUE_SLAB(s + 2, st2);
        }

        uint32_t sA = smb + st0 * STAGE_BYTES;
        uint32_t sB = sA + 2 * A_PHASE_BYTES;
#pragma unroll
        for (int kk = 0; kk < 2; kk++) {
            uint32_t b[8][2];
#pragma unroll
            for (int q = 0; q < 4; q++) {
                uint32_t addr = sB + (uint32_t)((wx * 64 + q * 16) * ROW_STRIDE)
                              + tbaseB + kk * 32;
                LDSM4(b[2 * q][0], b[2 * q][1], b[2 * q + 1][0], b[2 * q + 1][1], addr);
            }
#pragma unroll
            for (int p = 0; p < 2; p++) {
                uint32_t a0[4], a1[4];
                uint32_t aaddr = sA + p * A_PHASE_BYTES + tbaseA + kk * 32;
                LDSM4(a0[0], a0[1], a0[2], a0[3], aaddr);
                LDSM4(a1[0], a1[1], a1[2], a1[3], aaddr + 16 * ROW_STRIDE);
#pragma unroll
                for (int nf = 0; nf < 8; nf++) {
                    MMA16816(acc[0][nf], a0, b[nf][0], b[nf][1]);
                    MMA16816(acc[1][nf], a1, b[nf][0], b[nf][1]);
                }
            }
        }
        st0 = st0 + 1; if (st0 >= N_STAGES) st0 -= N_STAGES;
    }
#undef ISSUE_SLAB

    // fused argmin over this chunk's 256 columns (ascending index)
    int colbase = colchunk + wx * 64 + (lane & 3) * 2;
#pragma unroll
    for (int nf = 0; nf < 8; nf++) {
        int cidx = colbase + nf * 8;
#pragma unroll
        for (int m = 0; m < 2; m++) {
            float d0 = fmaf(-2.0f, acc[m][nf][0], x2v[m * 2]);
            float d1 = fmaf(-2.0f, acc[m][nf][1], x2v[m * 2]);
            float d2 = fmaf(-2.0f, acc[m][nf][2], x2v[m * 2 + 1]);
            float d3 = fmaf(-2.0f, acc[m][nf][3], x2v[m * 2 + 1]);
            if (d0 < bD[m * 2])     { bD[m * 2] = d0;     bI[m * 2] = cidx; }
            if (d1 < bD[m * 2])     { bD[m * 2] = d1;     bI[m * 2] = cidx + 1; }
            if (d2 < bD[m * 2 + 1]) { bD[m * 2 + 1] = d2; bI[m * 2 + 1] = cidx; }
            if (d3 < bD[m * 2 + 1]) { bD[m * 2 + 1] = d3; bI[m * 2 + 1] = cidx + 1; }
        }
    }

#pragma unroll
    for (int off = 1; off <= 2; off <<= 1) {
#pragma unroll
        for (int s = 0; s < 4; s++) {
            float od = __shfl_xor_sync(0xffffffffu, bD[s], off);
            int   oi = __shfl_xor_sync(0xffffffffu, bI[s], off);
            if (od < bD[s] || (od == bD[s] && oi < bI[s])) { bD[s] = od; bI[s] = oi; }
        }
    }

    if ((lane & 3) == 0) {
#pragma unroll
        for (int s = 0; s < 4; s++) {
            int row = rowbase + wy * 32 + (lane >> 2) + ((s & 1) ? 8 : 0) + (s >> 1) * 16;
            uint32_t u = __float_as_uint(bD[s]);
            u = (u & 0x80000000u) ? ~u : (u | 0x80000000u);
            unsigned long long key = ((unsigned long long)u << 32) | (unsigned)bI[s];
            atomicMin(&g_best[row], key);
        }
    }
}

// ---------------------------------------------------------------------------
__global__ void gather_kernel(const float* __restrict__ cb, float* __restrict__ out) {
    int t = blockIdx.x * blockDim.x + threadIdx.x;
    int n  = t & (NN - 1);
    int cg = t >> 15;
    int idx = (int)(unsigned)(g_best[n] & 0xffffffffu);
    float4 v = ((const float4*)cb)[idx * 128 + cg];
    int b = n >> 10, p = n & 1023;
    int c = cg << 2;
    float* o = out + (((size_t)(b * 512 + c)) << 10) + p;
    o[0]    = v.x;
    o[1024] = v.y;
    o[2048] = v.z;
    o[3072] = v.w;
}

__global__ void hist_kernel() {
    __shared__ int h[KK];
    int tid = threadIdx.x;
    for (int i = tid; i < KK; i += 256) h[i] = 0;
    __syncthreads();
    int base = blockIdx.x * 1024;
    for (int i = tid; i < 1024; i += 256)
        atomicAdd(&h[(int)(unsigned)(g_best[base + i] & 0xffffffffu)], 1);
    __syncthreads();
    for (int i = tid; i < KK; i += 256) if (h[i]) atomicAdd(&g_cnt[i], h[i]);
}

__global__ void entropy_kernel(float* __restrict__ out_scalars) {
    __shared__ float s[256];
    int tid = threadIdx.x;
    float acc = 0.0f;
    for (int k = tid; k < KK; k += 256) {
        int c = g_cnt[k];
        if (c > 0) {
            float p = (float)c / 32768.0f;
            acc += p * logf(p);
        }
    }
    s[tid] = acc;
    __syncthreads();
    for (int o = 128; o > 0; o >>= 1) {
        if (tid < o) s[tid] += s[tid + o];
        __syncthreads();
    }
    if (tid == 0) {
        float entropy = -s[0];
        float perp = expf(entropy);
        float pl = 1.0f / perp;
        out_scalars[0] = pl;
        out_scalars[1] = 0.25f * pl;
    }
}

// ---------------------------------------------------------------------------
extern "C" void kernel_launch(void* const* d_in, const int* in_sizes, int n_in,
                              void* d_out, int out_size) {
    const float* x  = (const float*)d_in[0];
    const float* cb = (const float*)d_in[1];
    float* out = (float*)d_out;

    cudaFuncSetAttribute(prep_kernel, cudaFuncAttributeMaxDynamicSharedMemorySize, PREP_SMEM);
    cudaFuncSetAttribute(gemm_hmma_kernel, cudaFuncAttributeMaxDynamicSharedMemorySize, GEMM_SMEM);

    init_kernel<<<NN / 256, 256>>>();
    cb_f16_kernel<<<1024, 256>>>(cb);
    prep_kernel<<<1024, 512, PREP_SMEM>>>(x);
    gemm_hmma_kernel<<<(NN / M_TILE) * (KK / N_TILE), 512, GEMM_SMEM>>>();
    gather_kernel<<<(NN * 128) / 256, 256>>>(cb, out);
    hist_kernel<<<NN / 1024, 256>>>();
    if (out_size >= QE + 2) {
        entropy_kernel<<<1, 256>>>(out + QE);
    }
}

// round 9
// speedup vs baseline: 3.3342x; 1.0377x over previous
#include <cuda_runtime.h>
#include <cuda_fp16.h>
#include <cstdint>
#include <math.h>

// Problem constants
#define NN   32768
#define KK   1024
#define QE   16777216

// GEMM tiling: CTA = 128 rows x 128 codes, 256 thr = 8 warps (4M x 2N)
#define M_TILE 128
#define N_TILE 128
#define K_SLABS 16             // 512 ch / 32 per slab
#define ROW_STRIDE 80          // 64B data + 16B pad (conflict-free ldsm)
#define A_PHASE_BYTES (128 * ROW_STRIDE)            // 10240
#define STAGE_BYTES (3 * A_PHASE_BYTES)             // 2 A planes + B = 30720
#define N_STAGES 3
#define GEMM_SMEM (N_STAGES * STAGE_BYTES)          // 92160 (x2 CTAs = 184320)
#define PREP_SMEM (65664 + 2048)

// Scratch (device globals; allocation-free). Slab-major:
// g_hi[slab 16][row 32768][16 u32] (16 u32 = 32 ch fp16 = 64B)
__device__ uint32_t g_hi[16 * NN * 16];
__device__ uint32_t g_mid[16 * NN * 16];
__device__ uint32_t g_cbh[16 * KK * 16];   // fp16 codebook [slab][code][16 u32]
__device__ float g_x2[NN];
__device__ unsigned long long g_best[NN];
__device__ int g_cnt[KK];

__device__ __forceinline__ uint32_t smem_u32(const void* p) {
    return (uint32_t)__cvta_generic_to_shared(p);
}

#define LDSM4(r0, r1, r2, r3, addr)                                           \
    asm volatile("ldmatrix.sync.aligned.m8n8.x4.shared.b16 {%0,%1,%2,%3}, [%4];" \
                 : "=r"(r0), "=r"(r1), "=r"(r2), "=r"(r3) : "r"(addr))

#define MMA16816(C, A, B0, B1)                                                \
    asm volatile("mma.sync.aligned.m16n8k16.row.col.f32.f16.f16.f32 "         \
                 "{%0,%1,%2,%3},{%4,%5,%6,%7},{%8,%9},{%0,%1,%2,%3};"         \
                 : "+f"((C)[0]), "+f"((C)[1]), "+f"((C)[2]), "+f"((C)[3])     \
                 : "r"((A)[0]), "r"((A)[1]), "r"((A)[2]), "r"((A)[3]),        \
                   "r"(B0), "r"(B1))

#define CP_ASYNC16(dst, src)                                                  \
    asm volatile("cp.async.cg.shared.global [%0], [%1], 16;" :: "r"(dst), "l"(src))
#define CP_COMMIT() asm volatile("cp.async.commit_group;")
#define CP_WAIT1()  asm volatile("cp.async.wait_group 1;")
#define CP_WAIT0()  asm volatile("cp.async.wait_group 0;")

// ---------------------------------------------------------------------------
// init: g_best = +inf keys, g_cnt = 0
// ---------------------------------------------------------------------------
__global__ void init_kernel() {
    int i = blockIdx.x * 256 + threadIdx.x;
    g_best[i] = 0xFFFFFFFFFFFFFFFFull;
    if (i < KK) g_cnt[i] = 0;
}

// ---------------------------------------------------------------------------
// codebook fp32 (+-1) -> fp16 (exact), slab-major
// ---------------------------------------------------------------------------
__global__ void cb_f16_kernel(const float* __restrict__ cb) {
    int i = blockIdx.x * 256 + threadIdx.x;   // code*256 + cw
    int code = i >> 8, cw = i & 255;
    float2 v = ((const float2*)cb)[i];
    __half2 h2 = __floats2half2_rn(v.x, v.y);
    uint32_t u; memcpy(&u, &h2, 4);
    g_cbh[(((size_t)(cw >> 4)) * KK + code) * 16 + (cw & 15)] = u;
}

// ---------------------------------------------------------------------------
// prep: xs = tanh(50x) via FMA-only exp2 + Newton rcp, 2-way fp16 split,
// transpose slab-major, ||xs||^2 + 512.
// ---------------------------------------------------------------------------
__global__ void __launch_bounds__(512, 2) prep_kernel(const float* __restrict__ x) {
    extern __shared__ char sm[];
    uint32_t* s_hm = (uint32_t*)sm;             // [32][513]  (hi | mid<<16)
    float* s_red = (float*)(sm + 65664);        // [512]

    int tid = threadIdx.x;
    int b   = blockIdx.x >> 5;
    int p0  = (blockIdx.x & 31) * 32;
    int p   = tid & 31;
    int cg  = tid >> 5;         // 0..15

    float acc = 0.0f;
#pragma unroll 4
    for (int j = 0; j < 32; j++) {
        int c = j * 16 + cg;
        float v = x[(b * 512 + c) * 1024 + p0 + p];
        float t = fmaxf(-144.26950408889634f * fabsf(v), -30.0f);
        float kf = t + 12582912.0f;
        int   ni = __float_as_int(kf) - 0x4B400000;
        float f  = t - (kf - 12582912.0f);
        float pe = 1.52527338e-5f;
        pe = fmaf(pe, f, 1.54035304e-4f);
        pe = fmaf(pe, f, 1.33335581e-3f);
        pe = fmaf(pe, f, 9.61812911e-3f);
        pe = fmaf(pe, f, 5.55041087e-2f);
        pe = fmaf(pe, f, 2.40226507e-1f);
        pe = fmaf(pe, f, 6.93147181e-1f);
        pe = fmaf(pe, f, 1.0f);
        float m = __int_as_float(__float_as_int(pe) + (ni << 23));
        float den = 1.0f + m;
        float r = fmaf(-0.5f, den, 1.45710678f);
        r = r * fmaf(-den, r, 2.0f);
        r = r * fmaf(-den, r, 2.0f);
        r = r * fmaf(-den, r, 2.0f);
        float w = (1.0f - m) * r;
        float xs = copysignf(w, v);
        acc = fmaf(w, w, acc);
        __half h = __float2half_rn(xs);
        float r1 = xs - __half2float(h);
        __half md = __float2half_rn(r1);
        s_hm[p * 513 + c] = (uint32_t)__half_as_ushort(h)
                          | ((uint32_t)__half_as_ushort(md) << 16);
    }
    s_red[tid] = acc;
    __syncthreads();

    if (tid < 32) {
        float t = 0.0f;
#pragma unroll
        for (int g = 0; g < 16; g++) t += s_red[g * 32 + tid];
        g_x2[b * 1024 + p0 + tid] = t + 512.0f;
    }

    int nb = b * 1024 + p0;
#pragma unroll 4
    for (int t = tid; t < 32 * 256; t += 512) {
        int r  = t >> 8;
        int cw = t & 255;
        uint32_t hm0 = s_hm[r * 513 + 2 * cw];
        uint32_t hm1 = s_hm[r * 513 + 2 * cw + 1];
        uint32_t hi_pair  = (hm0 & 0xffffu) | (hm1 << 16);
        uint32_t mid_pair = (hm0 >> 16) | (hm1 & 0xffff0000u);
        size_t gi = (((size_t)(cw >> 4)) * NN + nb + r) * 16 + (cw & 15);
        g_hi[gi]  = hi_pair;
        g_mid[gi] = mid_pair;
    }
}

// ---------------------------------------------------------------------------
// GEMM + fused argmin. grid = 256 M-tiles x 8 N-chunks (nc in low 3 bits).
// 256 threads = 8 warps (4M x 2N), warp tile 32x64, 2 fp16 split planes.
// 3-stage cp.async pipeline, one __syncthreads per slab, 2 CTAs/SM.
// ---------------------------------------------------------------------------
__global__ void __launch_bounds__(256, 2) gemm_hmma_kernel() {
    extern __shared__ char sm[];
    uint32_t smb = smem_u32(sm);

    int tid = threadIdx.x;
    int lane = tid & 31;
    int wid = tid >> 5;
    int wy = wid & 3;
    int wx = wid >> 2;          // 0..1
    int bid = blockIdx.x;
    int rowbase = (bid >> 3) * M_TILE;
    int colchunk = (bid & 7) * N_TILE;

    uint32_t tbaseA = (uint32_t)((wy * 32 + ((lane >> 3) & 1) * 8 + (lane & 7)) * ROW_STRIDE
                                 + (lane >> 4) * 16);
    uint32_t tbaseB = (uint32_t)(((lane >> 4) * 8 + (lane & 7)) * ROW_STRIDE
                                 + ((lane >> 3) & 1) * 16);

    const char* gA[2] = { (const char*)g_hi, (const char*)g_mid };

    float x2v[4];
#pragma unroll
    for (int s = 0; s < 4; s++)
        x2v[s] = g_x2[rowbase + wy * 32 + (lane >> 2) + ((s & 1) ? 8 : 0) + (s >> 1) * 16];

    float bD[4] = {INFINITY, INFINITY, INFINITY, INFINITY};
    int   bI[4] = {0, 0, 0, 0};

    float acc[2][8][4];
#pragma unroll
    for (int m = 0; m < 2; m++)
#pragma unroll
        for (int nf = 0; nf < 8; nf++)
#pragma unroll
            for (int j = 0; j < 4; j++) acc[m][nf][j] = 0.0f;

// 1536 16B chunks per slab: A 2 planes x128r x4c = 1024, B 128r x4c = 512.
#define ISSUE_SLAB(slab, stage)                                               \
    {                                                                         \
        uint32_t dstbase = smb + (stage) * STAGE_BYTES;                       \
        _Pragma("unroll")                                                     \
        for (int i = 0; i < 6; i++) {                                         \
            int id = tid + i * 256;                                           \
            if (id < 1024) {                                                  \
                int part = id >> 9;                                           \
                int r = (id >> 2) & 127;                                      \
                int c = id & 3;                                               \
                uint32_t dst = dstbase + part * A_PHASE_BYTES                 \
                             + r * ROW_STRIDE + c * 16;                       \
                const char* src = gA[part]                                    \
                    + ((size_t)(slab) * NN + rowbase + r) * 64 + c * 16;      \
                CP_ASYNC16(dst, src);                                         \
            } else {                                                          \
                int id2 = id - 1024;                                          \
                int r = id2 >> 2;                                             \
                int c = id2 & 3;                                              \
                uint32_t dst = dstbase + 2 * A_PHASE_BYTES                    \
                             + r * ROW_STRIDE + c * 16;                       \
                const char* src = (const char*)g_cbh                          \
                    + ((size_t)(slab) * KK + colchunk + r) * 64 + c * 16;     \
                CP_ASYNC16(dst, src);                                         \
            }                                                                 \
        }                                                                     \
        CP_COMMIT();                                                          \
    }

    // prologue: two slabs in flight
    ISSUE_SLAB(0, 0);
    ISSUE_SLAB(1, 1);

    int st0 = 0;                // stage of slab s
    for (int s = 0; s < K_SLABS; s++) {
        if (s + 1 < K_SLABS) { CP_WAIT1(); } else { CP_WAIT0(); }
        __syncthreads();

        // issue s+2 into the stage freed by slab s-1 (readers done at the sync)
        if (s + 2 < K_SLABS) {
            int st2 = st0 + 2; if (st2 >= N_STAGES) st2 -= N_STAGES;
            ISSUE_SLAB(s + 2, st2);
        }

        uint32_t sA = smb + st0 * STAGE_BYTES;
        uint32_t sB = sA + 2 * A_PHASE_BYTES;
#pragma unroll
        for (int kk = 0; kk < 2; kk++) {
            uint32_t b[8][2];
#pragma unroll
            for (int q = 0; q < 4; q++) {
                uint32_t addr = sB + (uint32_t)((wx * 64 + q * 16) * ROW_STRIDE)
                              + tbaseB + kk * 32;
                LDSM4(b[2 * q][0], b[2 * q][1], b[2 * q + 1][0], b[2 * q + 1][1], addr);
            }
#pragma unroll
            for (int p = 0; p < 2; p++) {
                uint32_t a0[4], a1[4];
                uint32_t aaddr = sA + p * A_PHASE_BYTES + tbaseA + kk * 32;
                LDSM4(a0[0], a0[1], a0[2], a0[3], aaddr);
                LDSM4(a1[0], a1[1], a1[2], a1[3], aaddr + 16 * ROW_STRIDE);
#pragma unroll
                for (int nf = 0; nf < 8; nf++) {
                    MMA16816(acc[0][nf], a0, b[nf][0], b[nf][1]);
                    MMA16816(acc[1][nf], a1, b[nf][0], b[nf][1]);
                }
            }
        }
        st0 = st0 + 1; if (st0 >= N_STAGES) st0 -= N_STAGES;
    }
#undef ISSUE_SLAB

    // fused argmin over this chunk's 128 columns (ascending index)
    int colbase = colchunk + wx * 64 + (lane & 3) * 2;
#pragma unroll
    for (int nf = 0; nf < 8; nf++) {
        int cidx = colbase + nf * 8;
#pragma unroll
        for (int m = 0; m < 2; m++) {
            float d0 = fmaf(-2.0f, acc[m][nf][0], x2v[m * 2]);
            float d1 = fmaf(-2.0f, acc[m][nf][1], x2v[m * 2]);
            float d2 = fmaf(-2.0f, acc[m][nf][2], x2v[m * 2 + 1]);
            float d3 = fmaf(-2.0f, acc[m][nf][3], x2v[m * 2 + 1]);
            if (d0 < bD[m * 2])     { bD[m * 2] = d0;     bI[m * 2] = cidx; }
            if (d1 < bD[m * 2])     { bD[m * 2] = d1;     bI[m * 2] = cidx + 1; }
            if (d2 < bD[m * 2 + 1]) { bD[m * 2 + 1] = d2; bI[m * 2 + 1] = cidx; }
            if (d3 < bD[m * 2 + 1]) { bD[m * 2 + 1] = d3; bI[m * 2 + 1] = cidx + 1; }
        }
    }

#pragma unroll
    for (int off = 1; off <= 2; off <<= 1) {
#pragma unroll
        for (int s = 0; s < 4; s++) {
            float od = __shfl_xor_sync(0xffffffffu, bD[s], off);
            int   oi = __shfl_xor_sync(0xffffffffu, bI[s], off);
            if (od < bD[s] || (od == bD[s] && oi < bI[s])) { bD[s] = od; bI[s] = oi; }
        }
    }

    if ((lane & 3) == 0) {
#pragma unroll
        for (int s = 0; s < 4; s++) {
            int row = rowbase + wy * 32 + (lane >> 2) + ((s & 1) ? 8 : 0) + (s >> 1) * 16;
            uint32_t u = __float_as_uint(bD[s]);
            u = (u & 0x80000000u) ? ~u : (u | 0x80000000u);
            unsigned long long key = ((unsigned long long)u << 32) | (unsigned)bI[s];
            atomicMin(&g_best[row], key);
        }
    }
}

// ---------------------------------------------------------------------------
__global__ void gather_kernel(const float* __restrict__ cb, float* __restrict__ out) {
    int t = blockIdx.x * blockDim.x + threadIdx.x;
    int n  = t & (NN - 1);
    int cg = t >> 15;
    int idx = (int)(unsigned)(g_best[n] & 0xffffffffu);
    float4 v = ((const float4*)cb)[idx * 128 + cg];
    int b = n >> 10, p = n & 1023;
    int c = cg << 2;
    float* o = out + (((size_t)(b * 512 + c)) << 10) + p;
    o[0]    = v.x;
    o[1024] = v.y;
    o[2048] = v.z;
    o[3072] = v.w;
}

__global__ void hist_kernel() {
    __shared__ int h[KK];
    int tid = threadIdx.x;
    for (int i = tid; i < KK; i += 256) h[i] = 0;
    __syncthreads();
    int base = blockIdx.x * 1024;
    for (int i = tid; i < 1024; i += 256)
        atomicAdd(&h[(int)(unsigned)(g_best[base + i] & 0xffffffffu)], 1);
    __syncthreads();
    for (int i = tid; i < KK; i += 256) if (h[i]) atomicAdd(&g_cnt[i], h[i]);
}

__global__ void entropy_kernel(float* __restrict__ out_scalars) {
    __shared__ float s[256];
    int tid = threadIdx.x;
    float acc = 0.0f;
    for (int k = tid; k < KK; k += 256) {
        int c = g_cnt[k];
        if (c > 0) {
            float p = (float)c / 32768.0f;
            acc += p * logf(p);
        }
    }
    s[tid] = acc;
    __syncthreads();
    for (int o = 128; o > 0; o >>= 1) {
        if (tid < o) s[tid] += s[tid + o];
        __syncthreads();
    }
    if (tid == 0) {
        float entropy = -s[0];
        float perp = expf(entropy);
        float pl = 1.0f / perp;
        out_scalars[0] = pl;
        out_scalars[1] = 0.25f * pl;
    }
}

// ---------------------------------------------------------------------------
extern "C" void kernel_launch(void* const* d_in, const int* in_sizes, int n_in,
                              void* d_out, int out_size) {
    const float* x  = (const float*)d_in[0];
    const float* cb = (const float*)d_in[1];
    float* out = (float*)d_out;

    cudaFuncSetAttribute(prep_kernel, cudaFuncAttributeMaxDynamicSharedMemorySize, PREP_SMEM);
    cudaFuncSetAttribute(gemm_hmma_kernel, cudaFuncAttributeMaxDynamicSharedMemorySize, GEMM_SMEM);

    init_kernel<<<NN / 256, 256>>>();
    cb_f16_kernel<<<1024, 256>>>(cb);
    prep_kernel<<<1024, 512, PREP_SMEM>>>(x);
    gemm_hmma_kernel<<<(NN / M_TILE) * (KK / N_TILE), 256, GEMM_SMEM>>>();
    gather_kernel<<<(NN * 128) / 256, 256>>>(cb, out);
    hist_kernel<<<NN / 1024, 256>>>();
    if (out_size >= QE + 2) {
        entropy_kernel<<<1, 256>>>(out + QE);
    }
}